// round 3
// baseline (speedup 1.0000x reference)
#include <cuda_runtime.h>

#define BB   256
#define SS   1024
#define HH   512
#define CC   10
#define GROUPS 16
#define CPG  8          // CTAs per group
#define BPG  16         // batch rows per group
#define JPC  64         // j rows per CTA
#define THREADS 128
#define K4   128        // HH/4
#define XCHUNK 64
#define WPH_LD 516      // padded row stride for w_ph in smem

// shared-memory layout (in floats)
#define OFF_W4   0                         // float4[K4*JPC] = 32768 floats (128 KB)
#define OFF_H    (K4 * JPC * 4)            // 32768 : h_s [16][512] (32 KB)
#define OFF_WPH  (OFF_H + BPG * HH)        // 40960 : w_ph [10][516]
#define OFF_X    (OFF_WPH + CC * WPH_LD)   // 46120 : x_s [16][64]
#define OFF_WX   (OFF_X + BPG * XCHUNK)    // 47144
#define OFF_BH   (OFF_WX + 64)
#define OFF_BP   (OFF_BH + 64)
#define OFF_RED  (OFF_BP + 16)
#define SMEM_FLOATS (OFF_RED + 128)
#define SMEM_BYTES  (SMEM_FLOATS * 4)      // 189,664 B

__device__ float    g_h[2][BB * HH];       // double-buffered hidden state (1 MB)
__device__ unsigned g_bar[GROUPS * 32];    // per-group barrier counters (128B apart)

__device__ __forceinline__ float2 ffma2(float2 a, float2 b, float2 c)
{
    float2 d;
    asm("{\n\t"
        ".reg .b64 A,Bq,Cq;\n\t"
        "mov.b64 A, {%2,%3};\n\t"
        "mov.b64 Bq, {%4,%5};\n\t"
        "mov.b64 Cq, {%6,%7};\n\t"
        "fma.rn.f32x2 Cq, A, Bq, Cq;\n\t"
        "mov.b64 {%0,%1}, Cq;\n\t"
        "}"
        : "=f"(d.x), "=f"(d.y)
        : "f"(a.x), "f"(a.y), "f"(b.x), "f"(b.y), "f"(c.x), "f"(c.y));
    return d;
}

__global__ void zero_bar_kernel()
{
    for (int i = threadIdx.x; i < GROUPS * 32; i += blockDim.x) g_bar[i] = 0u;
}

__global__ void __launch_bounds__(THREADS, 1)
rnn_kernel(const float* __restrict__ x,    const float* __restrict__ w_hx,
           const float* __restrict__ w_hh, const float* __restrict__ w_ph,
           const float* __restrict__ b_h,  const float* __restrict__ b_p,
           float* __restrict__ out)
{
    extern __shared__ float sm[];
    float4* w4   = (float4*)(sm + OFF_W4);   // w4[k4*JPC + j] = {w[4k4..4k4+3][j]}
    float*  h_s  = sm + OFF_H;
    float*  wph  = sm + OFF_WPH;
    float*  x_s  = sm + OFF_X;
    float*  wx_s = sm + OFF_WX;
    float*  bh_s = sm + OFF_BH;
    float*  bp_s = sm + OFF_BP;
    float*  red  = sm + OFF_RED;

    const int tid = threadIdx.x;
    const int grp = blockIdx.x / CPG;
    const int cta = blockIdx.x % CPG;
    const int j0  = cta * JPC;
    const int b0  = grp * BPG;

    // ---------------- one-time init ----------------
    // w_hh slice -> k-quad packed smem (global read coalesced along k)
    for (int i = tid; i < JPC * HH; i += THREADS) {
        int j = i >> 9, k = i & (HH - 1);
        ((float*)w4)[((k >> 2) * JPC + j) * 4 + (k & 3)] = w_hh[(j0 + j) * HH + k];
    }
    for (int i = tid; i < CC * HH; i += THREADS) {
        int c = i >> 9, j = i & (HH - 1);
        wph[c * WPH_LD + j] = w_ph[i];
    }
    if (tid < JPC) { wx_s[tid] = w_hx[j0 + tid]; bh_s[tid] = b_h[j0 + tid]; }
    if (tid < CC)  { bp_s[tid] = b_p[tid]; }
    for (int i = tid; i < BPG * HH; i += THREADS) h_s[i] = 0.f;   // h0 = 0
    __syncthreads();

    const int   jl    = tid & 63;            // j within CTA slice
    const int   bbase = (tid >> 6) << 3;     // 0 or 8 : 8 batch rows per thread
    const float wxj   = wx_s[jl];
    const float bhj   = bh_s[jl];

    unsigned* bar = &g_bar[grp * 32];

    for (int t = 0; t < SS; ++t) {
        // ---- stage x chunk every 64 steps ----
        if ((t & (XCHUNK - 1)) == 0) {
            for (int i = tid; i < BPG * XCHUNK; i += THREADS) {
                int bb = i >> 6, tt = i & 63;
                x_s[i] = x[(b0 + bb) * SS + t + tt];
            }
            __syncthreads();
        }

        // ---- GEMM: acc[b] = x*wx + b_h + sum_k h[b,k]*W[j,k] (even/odd packed)
        float2 acc[8];
        #pragma unroll
        for (int bb = 0; bb < 8; ++bb) {
            float xv = x_s[(bbase + bb) * XCHUNK + (t & 63)];
            acc[bb].x = fmaf(xv, wxj, bhj);
            acc[bb].y = 0.f;
        }
        const float4* w4p = w4 + jl;
        #pragma unroll 2
        for (int k4 = 0; k4 < K4; ++k4) {
            float4 wv = w4p[k4 * JPC];
            #pragma unroll
            for (int bb = 0; bb < 8; ++bb) {
                float4 hv = *(const float4*)(h_s + (bbase + bb) * HH + (k4 << 2));
                acc[bb] = ffma2(make_float2(hv.x, hv.y), make_float2(wv.x, wv.y), acc[bb]);
                acc[bb] = ffma2(make_float2(hv.z, hv.w), make_float2(wv.z, wv.w), acc[bb]);
            }
        }

        // ---- tanh + publish h_{t+1} slice to global (L2) ----
        const int p1 = (t + 1) & 1;
        float* gdst = &g_h[p1][0];
        #pragma unroll
        for (int bb = 0; bb < 8; ++bb) {
            float pre = acc[bb].x + acc[bb].y;
            pre = fminf(fmaxf(pre, -15.f), 15.f);
            float e  = __expf(2.f * pre);
            float hn = __fdividef(e - 1.f, e + 1.f);
            __stcg(&gdst[(b0 + bbase + bb) * HH + j0 + jl], hn);
        }

        // ---- group barrier (monotone counter, reset by prologue) ----
        __threadfence();
        __syncthreads();
        if (tid == 0) {
            atomicAdd(bar, 1u);
            const unsigned tgt = (unsigned)(CPG * (t + 1));
            while (*(volatile unsigned*)bar < tgt) __nanosleep(40);
        }
        __syncthreads();

        // ---- reload full h_{t+1} (16 x 512) from L2, bypass L1 ----
        {
            const float4* src = (const float4*)&g_h[p1][b0 * HH];
            float4*       dst = (float4*)h_s;
            #pragma unroll
            for (int i = 0; i < (BPG * HH / 4) / THREADS; ++i)   // 16 iters
                dst[tid + i * THREADS] = __ldcg(src + tid + i * THREADS);
        }
        __syncthreads();

        // ---- projection: this CTA emits preds for its 2 batch rows ----
        if (tid < 80) {
            int kq = tid / 20, rem = tid % 20;
            int bl = rem / 10, c = rem % 10;
            const float4* hrow = (const float4*)(h_s + (cta * 2 + bl) * HH) + kq * 32;
            const float4* wrow = (const float4*)(wph + c * WPH_LD) + kq * 32;
            float s0 = 0.f, s1 = 0.f;
            #pragma unroll 8
            for (int q = 0; q < 32; ++q) {
                float4 hv = hrow[q], wv = wrow[q];
                s0 = fmaf(hv.x, wv.x, s0); s1 = fmaf(hv.y, wv.y, s1);
                s0 = fmaf(hv.z, wv.z, s0); s1 = fmaf(hv.w, wv.w, s1);
            }
            red[tid] = s0 + s1;
        }
        __syncthreads();
        if (tid < 20) {
            int bl = tid / 10, c = tid % 10;
            float p = red[tid] + red[tid + 20] + red[tid + 40] + red[tid + 60] + bp_s[c];
            out[((b0 + cta * 2 + bl) * SS + t) * CC + c] = p;
        }
        // red/x_s reuse is guarded by the barrier-phase __syncthreads of the next step
    }
}

extern "C" void kernel_launch(void* const* d_in, const int* in_sizes, int n_in,
                              void* d_out, int out_size)
{
    const float* xx   = (const float*)d_in[0];
    const float* w_hx = (const float*)d_in[1];
    const float* w_hh = (const float*)d_in[2];
    const float* w_ph = (const float*)d_in[3];
    const float* b_h  = (const float*)d_in[4];
    const float* b_p  = (const float*)d_in[5];
    float* out = (float*)d_out;

    cudaFuncSetAttribute(rnn_kernel,
                         cudaFuncAttributeMaxDynamicSharedMemorySize, SMEM_BYTES);
    zero_bar_kernel<<<1, 128>>>();
    rnn_kernel<<<GROUPS * CPG, THREADS, SMEM_BYTES>>>(xx, w_hx, w_hh, w_ph, b_h, b_p, out);
}